// round 16
// baseline (speedup 1.0000x reference)
#include <cuda_runtime.h>
#include <cuda_fp16.h>
#include <cstdint>

// Problem constants (B=2, S=4096, D=H=512), softmax scale = sqrt(512/8)=8.
#define Bsz 2
#define Sq  4096
#define Dd  512
#define Hh  512
#define DW  (Dd * Hh)

// Scratch (device globals: allocation inside kernel_launch is forbidden).
__device__ __half g_xh  [(size_t)Bsz * Sq * Dd], g_xl [(size_t)Bsz * Sq * Dd];
__device__ __half g_Wqkh[2 * DW], g_Wqkl[2 * DW];      // (0.125*Wq | Wk), K-major
__device__ float  g_bqk [2 * Hh];                      // (0.125*bq | bk)
__device__ __half g_Wvh [DW], g_Wvl [DW];
__device__ __half g_Wmh [DW], g_Wml [DW];
__device__ __half g_qkh [(size_t)Bsz * Sq * 2 * Hh];   // q cols 0-511, k cols 512-1023
__device__ __half g_qkl [(size_t)Bsz * Sq * 2 * Hh];
__device__ float  g_v   [(size_t)Bsz * Sq * Hh];
__device__ __half g_vth [(size_t)Bsz * Sq * Hh], g_vtl[(size_t)Bsz * Sq * Hh];
__device__ float  g_sc  [(size_t)Bsz * Sq * Sq];       // 128 MB
__device__ __half g_ph  [(size_t)Bsz * Sq * Sq];       // 64 MB (unnormalized probs)
__device__ float  g_linv[(size_t)Bsz * Sq];            // 1/rowsum
__device__ __half g_ath [(size_t)Bsz * Sq * Hh];       // attn hi (mix is 2-term)

// ---------------------------------------------------------------------------
// helpers
// ---------------------------------------------------------------------------
__device__ __forceinline__ uint32_t smem_u32(const void* p) {
    uint32_t a;
    asm("{ .reg .u64 t; cvta.to.shared.u64 t, %1; cvt.u32.u64 %0, t; }"
        : "=r"(a) : "l"(p));
    return a;
}
__device__ __forceinline__ void cp16(uint32_t smem, const void* g) {
    asm volatile("cp.async.cg.shared.global [%0], [%1], 16;"
                 :: "r"(smem), "l"(g) : "memory");
}
#define CP_COMMIT() asm volatile("cp.async.commit_group;" ::: "memory")
#define CP_WAIT(n)  asm volatile("cp.async.wait_group %0;" :: "n"(n) : "memory")

#define LDSM4(r, addr)                                                        \
    asm volatile("ldmatrix.sync.aligned.m8n8.x4.shared.b16 "                  \
                 "{%0,%1,%2,%3}, [%4];"                                       \
                 : "=r"((r)[0]), "=r"((r)[1]), "=r"((r)[2]), "=r"((r)[3])     \
                 : "r"(addr))

// m16n8k16 fp16 mma, fp32 accum. row.col => both operands K-major (NT GEMM).
__device__ __forceinline__ void mma16(float* c, const uint32_t* a, const uint32_t* b) {
    asm volatile(
        "mma.sync.aligned.m16n8k16.row.col.f32.f16.f16.f32 "
        "{%0,%1,%2,%3}, {%4,%5,%6,%7}, {%8,%9}, {%0,%1,%2,%3};"
        : "+f"(c[0]), "+f"(c[1]), "+f"(c[2]), "+f"(c[3])
        : "r"(a[0]), "r"(a[1]), "r"(a[2]), "r"(a[3]), "r"(b[0]), "r"(b[1]));
}

// ---------------------------------------------------------------------------
// fp16x3 GEMM:  C = rowscale[r] * (scale * (A @ W^T) + bscale * bias)
// CTA tile 128x128, KC=32. 256 threads = 8 warps (2M x 4N), warp tile 64x32.
// smem: 64B rows, XOR swizzle (chunk ^= (row>>1)&3) -> conflict-free ldmatrix
// with ZERO padding: part 8KB, stage 32KB, 3 stages = 96KB => 2 CTAs/SM.
// Single __syncthreads per chunk (NSTG=3 reuse proof as before).
// ---------------------------------------------------------------------------
#define BM 128
#define BN 128
#define KC 32
#define PARTB  8192u                   // 128 rows * 64 B
#define STAGEB (4u * PARTB)            // 32 KB
#define NSTG 3
#define SMEM_SZ (NSTG * STAGEB)        // 96 KB

// swizzled byte offset within a part for (row, 16B-chunk)
__device__ __forceinline__ uint32_t swz(uint32_t row, uint32_t chunk) {
    return row * 64u + ((chunk ^ ((row >> 1) & 3u)) << 4);
}

__global__ __launch_bounds__(256, 2)
void k_hgemm(const __half* __restrict__ Ah, const __half* __restrict__ Al,
             const __half* __restrict__ Wh, const __half* __restrict__ Wl,
             const float* __restrict__ bias, const float* __restrict__ rowscale,
             float* __restrict__ Cf, __half* __restrict__ Ch,
             int M, int N, int K, int lda, int ldw, int ldc,
             float scale, float bscale,
             long long sA, long long sW, long long sC,
             int skip_lower, int diag_kstart)
{
    int nb = blockIdx.x, bz = blockIdx.z;
    int mb = blockIdx.y;
    if (skip_lower && nb < mb) return;          // block entirely masked (j < i)
    int hasAl = (Al != 0);
    Ah += (size_t)bz * sA;  if (hasAl) Al += (size_t)bz * sA;
    Wh += (size_t)bz * sW;  Wl += (size_t)bz * sW;
    if (Cf) Cf += (size_t)bz * sC;
    if (Ch) Ch += (size_t)bz * sC;
    if (rowscale) rowscale += (size_t)bz * M;

    extern __shared__ uint32_t sm32[];
    uint32_t smb = smem_u32(sm32);

    int tid  = threadIdx.x;
    int warp = tid >> 5, lane = tid & 31;
    int wm = warp >> 2, wn = warp & 3;          // 2 x 4 warp grid
    int g  = lane >> 2, q4 = lane & 3;
    int m0 = mb * BM, n0 = nb * BN;

    int kt0 = diag_kstart ? m0 : 0;
    int nch = (K - kt0) / KC;

    float acc[4][4][4];
    #pragma unroll
    for (int i = 0; i < 4; i++)
        #pragma unroll
        for (int j = 0; j < 4; j++)
            #pragma unroll
            for (int r = 0; r < 4; r++) acc[i][j][r] = 0.f;

    // A fragment lane addressing (4 m16 tiles per warp)
    uint32_t arow[4], arx[4];
    #pragma unroll
    for (int tm = 0; tm < 4; tm++) {
        uint32_t row = (uint32_t)(wm * 64 + tm * 16 + (lane & 15));
        arow[tm] = row * 64u;
        arx[tm]  = (row >> 1) & 3u;
    }
    uint32_t a_hi4 = (uint32_t)(lane >> 4);     // chunk select within k16

    // B fragment lane addressing (2 n16 pairs per warp)
    uint32_t brow[2], brx[2];
    #pragma unroll
    for (int p = 0; p < 2; p++) {
        uint32_t row = (uint32_t)(wn * 32 + p * 16 + (lane & 7) + ((lane >> 4) & 1) * 8);
        brow[p] = row * 64u;
        brx[p]  = (row >> 1) & 3u;
    }
    uint32_t b_sel = (uint32_t)((lane >> 3) & 1);

    // loader: 256 threads, per part 128 rows x 4 chunks of 16B
    int lrow2 = tid >> 2;                       // 0..63
    int lch   = tid & 3;                        // 16B chunk in 64B row
    auto load_stage = [&](uint32_t sb, int kt) {
        #pragma unroll
        for (int j = 0; j < 2; j++) {
            uint32_t row = (uint32_t)(j * 64 + lrow2);
            uint32_t so  = swz(row, (uint32_t)lch);
            size_t ga = (size_t)(m0 + (int)row) * lda + kt + lch * 8;
            size_t gw = (size_t)(n0 + (int)row) * ldw + kt + lch * 8;
            cp16(sb + so,              Ah + ga);
            if (hasAl) cp16(sb + PARTB + so, Al + ga);
            cp16(sb + 2 * PARTB + so,  Wh + gw);
            cp16(sb + 3 * PARTB + so,  Wl + gw);
        }
    };

    load_stage(smb, kt0);
    CP_COMMIT();
    if (nch > 1) { load_stage(smb + STAGEB, kt0 + KC); CP_COMMIT(); }

    for (int ic = 0; ic < nch; ic++) {
        if (ic + 1 < nch) { CP_WAIT(1); } else { CP_WAIT(0); }
        __syncthreads();   // stage ic visible; stage (ic+2)%3 == (ic-1)%3 is
                           // free for the prefetch below (all warps passed it)
        if (ic + 2 < nch) {
            load_stage(smb + (uint32_t)((ic + 2) % NSTG) * STAGEB,
                       kt0 + (ic + 2) * KC);
            CP_COMMIT();
        }

        uint32_t sbase = smb + (uint32_t)(ic % NSTG) * STAGEB;

        #pragma unroll
        for (int ks = 0; ks < 2; ks++) {        // 2 x k16 per KC=32 chunk
            uint32_t ach = (uint32_t)(ks * 2) + a_hi4;
            uint32_t bch = (uint32_t)(ks * 2) + b_sel;

            uint32_t ah[4][4];
            #pragma unroll
            for (int tm = 0; tm < 4; tm++)
                LDSM4(ah[tm], sbase + arow[tm] + ((ach ^ arx[tm]) << 4));
            uint32_t bh[2][4], bl[2][4];
            #pragma unroll
            for (int p = 0; p < 2; p++) {
                uint32_t bo = brow[p] + ((bch ^ brx[p]) << 4);
                LDSM4(bh[p], sbase + 2 * PARTB + bo);
                LDSM4(bl[p], sbase + 3 * PARTB + bo);
            }

            // term-major: 16 independent MMAs between accumulator reuses
            #pragma unroll
            for (int tn = 0; tn < 4; tn++) {
                const uint32_t* bhp = &bh[tn >> 1][(tn & 1) * 2];
                #pragma unroll
                for (int tm = 0; tm < 4; tm++)
                    mma16(acc[tm][tn], ah[tm], bhp);           // hi*hi
            }
            #pragma unroll
            for (int tn = 0; tn < 4; tn++) {
                const uint32_t* blp = &bl[tn >> 1][(tn & 1) * 2];
                #pragma unroll
                for (int tm = 0; tm < 4; tm++)
                    mma16(acc[tm][tn], ah[tm], blp);           // hi*lo
            }
            if (hasAl) {
                uint32_t al[4][4];
                #pragma unroll
                for (int tm = 0; tm < 4; tm++)
                    LDSM4(al[tm], sbase + PARTB + arow[tm] + ((ach ^ arx[tm]) << 4));
                #pragma unroll
                for (int tn = 0; tn < 4; tn++) {
                    const uint32_t* bhp = &bh[tn >> 1][(tn & 1) * 2];
                    #pragma unroll
                    for (int tm = 0; tm < 4; tm++)
                        mma16(acc[tm][tn], al[tm], bhp);       // lo*hi
                }
            }
        }
    }

    // ---- epilogue ----
    #pragma unroll
    for (int tm = 0; tm < 4; tm++) {
        int r = m0 + wm * 64 + tm * 16 + g;
        float rs0 = 1.f, rs1 = 1.f;
        if (rowscale) { rs0 = rowscale[r]; rs1 = rowscale[r + 8]; }
        #pragma unroll
        for (int tn = 0; tn < 4; tn++) {
            int cc = n0 + wn * 32 + tn * 8 + q4 * 2;
            float bv0 = 0.f, bv1 = 0.f;
            if (bias) {
                bv0 = bscale * __ldg(bias + cc);
                bv1 = bscale * __ldg(bias + cc + 1);
            }
            float v00 = (scale * acc[tm][tn][0] + bv0) * rs0;
            float v01 = (scale * acc[tm][tn][1] + bv1) * rs0;
            float v10 = (scale * acc[tm][tn][2] + bv0) * rs1;
            float v11 = (scale * acc[tm][tn][3] + bv1) * rs1;
            if (Cf) {
                *(float2*)(Cf + (size_t)r * ldc + cc)       = make_float2(v00, v01);
                *(float2*)(Cf + (size_t)(r + 8) * ldc + cc) = make_float2(v10, v11);
            }
            if (Ch) {
                __half h00 = __float2half_rn(v00), h01 = __float2half_rn(v01);
                __half h10 = __float2half_rn(v10), h11 = __float2half_rn(v11);
                *(__half2*)(Ch + (size_t)r * ldc + cc)       = __halves2half2(h00, h01);
                *(__half2*)(Ch + (size_t)(r + 8) * ldc + cc) = __halves2half2(h10, h11);
            }
        }
    }
}

// q/k projection variant: writes hi AND lo pair outputs (always 3-term).
__global__ __launch_bounds__(256, 2)
void k_hgemm_hl(const __half* __restrict__ Ah, const __half* __restrict__ Al,
                const __half* __restrict__ Wh, const __half* __restrict__ Wl,
                const float* __restrict__ bias,
                __half* __restrict__ Ch, __half* __restrict__ Cl,
                int M, int N, int K, int lda, int ldw, int ldc)
{
    int nb = blockIdx.x, mb = blockIdx.y;
    extern __shared__ uint32_t sm32[];
    uint32_t smb = smem_u32(sm32);

    int tid  = threadIdx.x;
    int warp = tid >> 5, lane = tid & 31;
    int wm = warp >> 2, wn = warp & 3;
    int g  = lane >> 2, q4 = lane & 3;
    int m0 = mb * BM, n0 = nb * BN;
    int nch = K / KC;

    float acc[4][4][4];
    #pragma unroll
    for (int i = 0; i < 4; i++)
        #pragma unroll
        for (int j = 0; j < 4; j++)
            #pragma unroll
            for (int r = 0; r < 4; r++) acc[i][j][r] = 0.f;

    uint32_t arow[4], arx[4];
    #pragma unroll
    for (int tm = 0; tm < 4; tm++) {
        uint32_t row = (uint32_t)(wm * 64 + tm * 16 + (lane & 15));
        arow[tm] = row * 64u;
        arx[tm]  = (row >> 1) & 3u;
    }
    uint32_t a_hi4 = (uint32_t)(lane >> 4);
    uint32_t brow[2], brx[2];
    #pragma unroll
    for (int p = 0; p < 2; p++) {
        uint32_t row = (uint32_t)(wn * 32 + p * 16 + (lane & 7) + ((lane >> 4) & 1) * 8);
        brow[p] = row * 64u;
        brx[p]  = (row >> 1) & 3u;
    }
    uint32_t b_sel = (uint32_t)((lane >> 3) & 1);

    int lrow2 = tid >> 2;
    int lch   = tid & 3;
    auto load_stage = [&](uint32_t sb, int kt) {
        #pragma unroll
        for (int j = 0; j < 2; j++) {
            uint32_t row = (uint32_t)(j * 64 + lrow2);
            uint32_t so  = swz(row, (uint32_t)lch);
            size_t ga = (size_t)(m0 + (int)row) * lda + kt + lch * 8;
            size_t gw = (size_t)(n0 + (int)row) * ldw + kt + lch * 8;
            cp16(sb + so,              Ah + ga);
            cp16(sb + PARTB + so,      Al + ga);
            cp16(sb + 2 * PARTB + so,  Wh + gw);
            cp16(sb + 3 * PARTB + so,  Wl + gw);
        }
    };

    load_stage(smb, 0);
    CP_COMMIT();
    if (nch > 1) { load_stage(smb + STAGEB, KC); CP_COMMIT(); }

    for (int ic = 0; ic < nch; ic++) {
        if (ic + 1 < nch) { CP_WAIT(1); } else { CP_WAIT(0); }
        __syncthreads();
        if (ic + 2 < nch) {
            load_stage(smb + (uint32_t)((ic + 2) % NSTG) * STAGEB, (ic + 2) * KC);
            CP_COMMIT();
        }
        uint32_t sbase = smb + (uint32_t)(ic % NSTG) * STAGEB;

        #pragma unroll
        for (int ks = 0; ks < 2; ks++) {
            uint32_t ach = (uint32_t)(ks * 2) + a_hi4;
            uint32_t bch = (uint32_t)(ks * 2) + b_sel;
            uint32_t ah[4][4];
            #pragma unroll
            for (int tm = 0; tm < 4; tm++)
                LDSM4(ah[tm], sbase + arow[tm] + ((ach ^ arx[tm]) << 4));
            uint32_t bh[2][4], bl[2][4];
            #pragma unroll
            for (int p = 0; p < 2; p++) {
                uint32_t bo = brow[p] + ((bch ^ brx[p]) << 4);
                LDSM4(bh[p], sbase + 2 * PARTB + bo);
                LDSM4(bl[p], sbase + 3 * PARTB + bo);
            }
            #pragma unroll
            for (int tn = 0; tn < 4; tn++) {
                const uint32_t* bhp = &bh[tn >> 1][(tn & 1) * 2];
                #pragma unroll
                for (int tm = 0; tm < 4; tm++)
                    mma16(acc[tm][tn], ah[tm], bhp);
            }
            #pragma unroll
            for (int tn = 0; tn < 4; tn++) {
                const uint32_t* blp = &bl[tn >> 1][(tn & 1) * 2];
                #pragma unroll
                for (int tm = 0; tm < 4; tm++)
                    mma16(acc[tm][tn], ah[tm], blp);
            }
            {
                uint32_t al[4][4];
                #pragma unroll
                for (int tm = 0; tm < 4; tm++)
                    LDSM4(al[tm], sbase + PARTB + arow[tm] + ((ach ^ arx[tm]) << 4));
                #pragma unroll
                for (int tn = 0; tn < 4; tn++) {
                    const uint32_t* bhp = &bh[tn >> 1][(tn & 1) * 2];
                    #pragma unroll
                    for (int tm = 0; tm < 4; tm++)
                        mma16(acc[tm][tn], al[tm], bhp);
                }
            }
        }
    }

    #pragma unroll
    for (int tm = 0; tm < 4; tm++) {
        int r = m0 + wm * 64 + tm * 16 + g;
        #pragma unroll
        for (int tn = 0; tn < 4; tn++) {
            int cc = n0 + wn * 32 + tn * 8 + q4 * 2;
            float bv0 = __ldg(bias + cc);
            float bv1 = __ldg(bias + cc + 1);
            float v00 = acc[tm][tn][0] + bv0;
            float v01 = acc[tm][tn][1] + bv1;
            float v10 = acc[tm][tn][2] + bv0;
            float v11 = acc[tm][tn][3] + bv1;
            __half h00 = __float2half_rn(v00), h01 = __float2half_rn(v01);
            __half h10 = __float2half_rn(v10), h11 = __float2half_rn(v11);
            *(__half2*)(Ch + (size_t)r * ldc + cc)       = __halves2half2(h00, h01);
            *(__half2*)(Ch + (size_t)(r + 8) * ldc + cc) = __halves2half2(h10, h11);
            *(__half2*)(Cl + (size_t)r * ldc + cc) = __halves2half2(
                __float2half_rn(v00 - __half2float(h00)),
                __float2half_rn(v01 - __half2float(h01)));
            *(__half2*)(Cl + (size_t)(r + 8) * ldc + cc) = __halves2half2(
                __float2half_rn(v10 - __half2float(h10)),
                __float2half_rn(v11 - __half2float(h11)));
        }
    }
}

// ---------------------------------------------------------------------------
// Fused prep: split x; build (0.125*Wq | Wk) and (0.125*bq | bk); split Wv, Wm.
// ---------------------------------------------------------------------------
__global__ __launch_bounds__(256)
void k_prep(const float* __restrict__ x,
            const float* __restrict__ Wq, const float* __restrict__ bq,
            const float* __restrict__ Wk, const float* __restrict__ bk,
            const float* __restrict__ Wv, const float* __restrict__ Wm)
{
    int stride = gridDim.x * 256;
    int gid = blockIdx.x * 256 + threadIdx.x;

    for (int i = gid; i < Bsz * Sq * Dd; i += stride) {
        float v = x[i];
        __half h = __float2half_rn(v);
        g_xh[i] = h;
        g_xl[i] = __float2half_rn(v - __half2float(h));
    }
    for (int i = gid; i < DW; i += stride) {
        float wq = 0.125f * Wq[i];               // exact (power of 2)
        __half h = __float2half_rn(wq);
        g_Wqkh[i] = h;
        g_Wqkl[i] = __float2half_rn(wq - __half2float(h));
        float wk = Wk[i];
        h = __float2half_rn(wk);
        g_Wqkh[DW + i] = h;
        g_Wqkl[DW + i] = __float2half_rn(wk - __half2float(h));
        float wv = Wv[i];
        h = __float2half_rn(wv);
        g_Wvh[i] = h;
        g_Wvl[i] = __float2half_rn(wv - __half2float(h));
        float wm = Wm[i];
        h = __float2half_rn(wm);
        g_Wmh[i] = h;
        g_Wml[i] = __float2half_rn(wm - __half2float(h));
    }
    for (int i = gid; i < Hh; i += stride) {
        g_bqk[i]      = 0.125f * bq[i];
        g_bqk[Hh + i] = bk[i];
    }
}

// ---------------------------------------------------------------------------
// Row softmax, single gmem read (row buffered in smem), unnormalized fp16
// probs for j in [i, S) (zeros for the in-tile prefix) + 1/rowsum.
// ---------------------------------------------------------------------------
__global__ __launch_bounds__(256)
void k_softmax(const float* __restrict__ Sc, __half* __restrict__ Ph,
               float* __restrict__ Linv)
{
    extern __shared__ float rowbuf[];
    __shared__ float red[256];
    int i = blockIdx.x;
    int b = blockIdx.y;
    size_t off = ((size_t)b * Sq + i) * Sq;
    const float* row = Sc + off;
    __half* ph = Ph + off;
    int t = threadIdx.x;

    float m = -3.402823466e38f;
    for (int j = i + t; j < Sq; j += 256) {
        float s = row[j];
        rowbuf[j] = s;
        m = fmaxf(m, s);
    }
    red[t] = m; __syncthreads();
    for (int s = 128; s > 0; s >>= 1) {
        if (t < s) red[t] = fmaxf(red[t], red[t + s]);
        __syncthreads();
    }
    m = red[0];
    __syncthreads();

    float l = 0.f;
    for (int j = i + t; j < Sq; j += 256) {
        float e = __expf(rowbuf[j] - m);
        l += e;
        ph[j] = __float2half_rn(e);
    }
    int i0 = i & ~(BM - 1);
    for (int j = i0 + t; j < i; j += 256) ph[j] = __float2half_rn(0.f);

    red[t] = l; __syncthreads();
    for (int s = 128; s > 0; s >>= 1) {
        if (t < s) red[t] += red[t + s];
        __syncthreads();
    }
    if (t == 0) Linv[(size_t)b * Sq + i] = 1.0f / red[0];
}

// ---------------------------------------------------------------------------
// Transpose v [S,H] -> vt [H,S] per batch, splitting to fp16 hi/lo.
// ---------------------------------------------------------------------------
__global__ __launch_bounds__(256)
void k_transpose_split(const float* __restrict__ V, __half* __restrict__ Th,
                       __half* __restrict__ Tl)
{
    __shared__ float t[32][33];
    int bz = blockIdx.z;
    const float* Vb = V + (size_t)bz * Sq * Hh;
    __half* Hb = Th + (size_t)bz * Sq * Hh;
    __half* Lb = Tl + (size_t)bz * Sq * Hh;
    int c0 = blockIdx.x * 32, r0 = blockIdx.y * 32;
    int tx = threadIdx.x & 31, ty = threadIdx.x >> 5;
    #pragma unroll
    for (int i = ty; i < 32; i += 8)
        t[i][tx] = Vb[(size_t)(r0 + i) * Hh + c0 + tx];
    __syncthreads();
    #pragma unroll
    for (int i = ty; i < 32; i += 8) {
        float v = t[tx][i];
        __half h = __float2half_rn(v);
        size_t o = (size_t)(c0 + i) * Sq + r0 + tx;
        Hb[o] = h;
        Lb[o] = __float2half_rn(v - __half2float(h));
    }
}

// ---------------------------------------------------------------------------
extern "C" void kernel_launch(void* const* d_in, const int* in_sizes, int n_in,
                              void* d_out, int out_size)
{
    (void)in_sizes; (void)n_in; (void)out_size;
    const float* x  = (const float*)d_in[0];
    const float* Wq = (const float*)d_in[1];
    const float* bq = (const float*)d_in[2];
    const float* Wk = (const float*)d_in[3];
    const float* bk = (const float*)d_in[4];
    const float* Wv = (const float*)d_in[5];
    const float* bv = (const float*)d_in[6];
    const float* Wm = (const float*)d_in[7];
    const float* bm = (const float*)d_in[8];
    float* out = (float*)d_out;

    __half *xh, *xl, *Wqkh, *Wqkl, *Wvh, *Wvl, *Wmh, *Wml;
    __half *qkh, *qkl, *vth, *vtl, *ph, *ath;
    float *v, *sc, *linv, *bqk;
    cudaGetSymbolAddress((void**)&xh,   g_xh);   cudaGetSymbolAddress((void**)&xl,   g_xl);
    cudaGetSymbolAddress((void**)&Wqkh, g_Wqkh); cudaGetSymbolAddress((void**)&Wqkl, g_Wqkl);
    cudaGetSymbolAddress((void**)&bqk,  g_bqk);
    cudaGetSymbolAddress((void**)&Wvh,  g_Wvh);  cudaGetSymbolAddress((void**)&Wvl,  g_Wvl);
    cudaGetSymbolAddress((void**)&Wmh,  g_Wmh);  cudaGetSymbolAddress((void**)&Wml,  g_Wml);
    cudaGetSymbolAddress((void**)&qkh,  g_qkh);  cudaGetSymbolAddress((void**)&qkl,  g_qkl);
    cudaGetSymbolAddress((void**)&v,    g_v);
    cudaGetSymbolAddress((void**)&vth,  g_vth);  cudaGetSymbolAddress((void**)&vtl,  g_vtl);
    cudaGetSymbolAddress((void**)&sc,   g_sc);
    cudaGetSymbolAddress((void**)&ph,   g_ph);
    cudaGetSymbolAddress((void**)&linv, g_linv);
    cudaGetSymbolAddress((void**)&ath,  g_ath);

    cudaFuncSetAttribute(k_hgemm,    cudaFuncAttributeMaxDynamicSharedMemorySize, SMEM_SZ);
    cudaFuncSetAttribute(k_hgemm_hl, cudaFuncAttributeMaxDynamicSharedMemorySize, SMEM_SZ);
    cudaFuncSetAttribute(k_softmax,  cudaFuncAttributeMaxDynamicSharedMemorySize, Sq * 4);

    dim3 blk(256);

    // Fused prep: split x / weights, build concat qk weight + bias.
    k_prep<<<2048, 256>>>(x, Wq, bq, Wk, bk, Wv, Wm);

    // q|k projection (one GEMM, N=1024; 0.125 folded into Wq/bq exactly).
    k_hgemm_hl<<<dim3(2 * Hh / BN, (Bsz * Sq) / BM, 1), blk, SMEM_SZ>>>(
        xh, xl, Wqkh, Wqkl, bqk, qkh, qkl,
        Bsz * Sq, 2 * Hh, Dd, Dd, Dd, 2 * Hh);

    // v projection (fp32 out).
    k_hgemm<<<dim3(Hh / BN, (Bsz * Sq) / BM, 1), blk, SMEM_SZ>>>(
        xh, xl, Wvh, Wvl, bv, (float*)0, v, (__half*)0,
        Bsz * Sq, Hh, Dd, Dd, Dd, Hh, 1.0f, 1.0f, 0, 0, 0, 0, 0);

    // Scores (fp32), upper-triangular blocks only: q/k read from qk buffer.
    k_hgemm<<<dim3(Sq / BN, Sq / BM, Bsz), blk, SMEM_SZ>>>(
        qkh, qkl, qkh + Hh, qkl + Hh, (const float*)0, (float*)0, sc, (__half*)0,
        Sq, Sq, Hh, 2 * Hh, 2 * Hh, Sq, 1.0f, 0.0f,
        (long long)Sq * 2 * Hh, (long long)Sq * 2 * Hh, (long long)Sq * Sq, 1, 0);

    // softmax -> unnormalized fp16 probs + inv rowsum.
    k_softmax<<<dim3(Sq, Bsz), 256, Sq * 4>>>(sc, ph, linv);

    // vt = v^T (split), then attn = (P @ v) * inv_l, 2-term; attn hi only.
    k_transpose_split<<<dim3(Hh / 32, Sq / 32, Bsz), 256>>>(v, vth, vtl);
    k_hgemm<<<dim3(Hh / BN, Sq / BM, Bsz), blk, SMEM_SZ>>>(
        ph, (__half*)0, vth, vtl, (const float*)0, linv, (float*)0, ath,
        Sq, Hh, Sq, Sq, Sq, Hh, 1.0f, 0.0f,
        (long long)Sq * Sq, (long long)Sq * Hh, (long long)Sq * Hh, 0, 1);

    // out = 8 * attn @ Wm^T + bm  (2-term).
    k_hgemm<<<dim3(Hh / BN, (Bsz * Sq) / BM, 1), blk, SMEM_SZ>>>(
        ath, (__half*)0, Wmh, Wml, bm, (float*)0, out, (__half*)0,
        Bsz * Sq, Hh, Dd, Dd, Dd, Hh, 8.0f, 1.0f, 0, 0, 0, 0, 0);
}